// round 17
// baseline (speedup 1.0000x reference)
#include <cuda_runtime.h>
#include <cuda_fp16.h>
#include <math.h>
#include <stdint.h>

#define S_LEN   2048
#define DMODEL  1024
#define NHEADS  16
#define WINDOW  256
#define LN_EPS  1e-5f

// ---------------- scratch (no allocations allowed) ----------------
__device__ float  g_o0[(size_t)S_LEN * DMODEL];       // out-proj partial 0
__device__ float  g_o1[(size_t)S_LEN * DMODEL];       // out-proj partial 1

// single fp16 operands
__device__ __half g_x16[(size_t)S_LEN * DMODEL];      // x fp16
__device__ __half g_a16[(size_t)S_LEN * DMODEL];      // attention out fp16
__device__ __half g_wq[(size_t)3 * DMODEL * DMODEL];  // W_qkv^T [3072,1024]
__device__ __half g_wo[(size_t)DMODEL * DMODEL];      // W_out^T [1024,1024]

// attention operands (produced directly by QKV GEMM epilogue)
__device__ __half g_q[(size_t)S_LEN * DMODEL];   // q (pre-scaled 1/8, roped)
__device__ __half g_k[(size_t)S_LEN * DMODEL];   // k (roped)
__device__ __half g_v[(size_t)DMODEL * S_LEN];   // V^T: [h*64+d][s]

// RoPE cos/sin table: [s][j] -> (cos, sin), j = 0..31
__device__ float2 g_cs[(size_t)S_LEN * 32];

// =====================================================================
// warp-level tensor-core helpers (sm_80+ baseline)
// =====================================================================
__device__ __forceinline__ uint32_t smem_u32(const void* p) {
    uint32_t a;
    asm("{ .reg .u64 t; cvta.to.shared.u64 t, %1; cvt.u32.u64 %0, t; }" : "=r"(a) : "l"(p));
    return a;
}
__device__ __forceinline__ void ldsm_x4(uint32_t* r, uint32_t addr) {
    asm volatile("ldmatrix.sync.aligned.m8n8.x4.shared.b16 {%0,%1,%2,%3}, [%4];"
                 : "=r"(r[0]), "=r"(r[1]), "=r"(r[2]), "=r"(r[3]) : "r"(addr));
}
__device__ __forceinline__ void mma_f16(float* d, const uint32_t* a, const uint32_t* b) {
    asm volatile(
        "mma.sync.aligned.m16n8k16.row.col.f32.f16.f16.f32 "
        "{%0,%1,%2,%3}, {%4,%5,%6,%7}, {%8,%9}, {%0,%1,%2,%3};"
        : "+f"(d[0]), "+f"(d[1]), "+f"(d[2]), "+f"(d[3])
        : "r"(a[0]), "r"(a[1]), "r"(a[2]), "r"(a[3]), "r"(b[0]), "r"(b[1]));
}
__device__ __forceinline__ void cp16(uint32_t dst, const void* src) {
    asm volatile("cp.async.cg.shared.global [%0], [%1], 16;" :: "r"(dst), "l"(src));
}
__device__ __forceinline__ void cp_commit() {
    asm volatile("cp.async.commit_group;" ::: "memory");
}
template <int N>
__device__ __forceinline__ void cp_wait() {
    asm volatile("cp.async.wait_group %0;" :: "n"(N) : "memory");
}

#define SWZ128(bo) ((bo) ^ (((bo) >> 3) & 0x70))

__device__ __forceinline__ uint32_t pack_hf2(float a, float b) {
    __half2 p = {__float2half_rn(a), __float2half_rn(b)};
    return *(uint32_t*)&p;
}

// =====================================================================
// FUSED prep: [0,3072)    Wqkv transpose -> g_wq
//             [3072,4096) Wout transpose -> g_wo
//             [4096,4608) x -> fp16
//             [4608,4864) RoPE cos/sin table
// =====================================================================
__device__ __forceinline__ void wtrans_body(
    const float* __restrict__ W, __half* __restrict__ out,
    int K, int N, int bn, int bk)
{
    __shared__ float t[32][33];
    const int tx = threadIdx.x & 31;
    const int ty = threadIdx.x >> 5;
#pragma unroll
    for (int i = 0; i < 32; i += 8)
        t[ty + i][tx] = W[(size_t)(bk + ty + i) * N + bn + tx];
    __syncthreads();
#pragma unroll
    for (int i = 0; i < 32; i += 8)
        out[(size_t)(bn + ty + i) * K + bk + tx] = __float2half_rn(t[tx][ty + i]);
}

__global__ void __launch_bounds__(256) prep_kernel(
    const float* __restrict__ x, const float* __restrict__ Wqkv,
    const float* __restrict__ Wout)
{
    const int b = blockIdx.x;
    if (b < 3072) {
        wtrans_body(Wqkv, g_wq, DMODEL, 3 * DMODEL, (b % 96) * 32, (b / 96) * 32);
    } else if (b < 4096) {
        const int i2 = b - 3072;
        wtrans_body(Wout, g_wo, DMODEL, DMODEL, (i2 % 32) * 32, (i2 / 32) * 32);
    } else if (b < 4608) {
        const int i3 = b - 4096;
        const int n4 = S_LEN * DMODEL / 4;
        const float4* in = (const float4*)x;
        uint2* out = (uint2*)g_x16;
        for (int i = i3 * 256 + threadIdx.x; i < n4; i += 512 * 256) {
            float4 v = in[i];
            out[i] = make_uint2(pack_hf2(v.x, v.y), pack_hf2(v.z, v.w));
        }
    } else {
        const int idx = (b - 4608) * 256 + threadIdx.x;   // 65536 entries
        const int s = idx >> 5;
        const int j = idx & 31;
        const float LOG2_1E4 = 13.28771237954945f;
        float inv = exp2f(-(float)j * (LOG2_1E4 / 32.0f));
        float sn, cs;
        sincosf((float)s * inv, &sn, &cs);
        g_cs[idx] = make_float2(cs, sn);
    }
}

// =====================================================================
// single-fp16 tensor-core GEMM.
// CTA 128x128, K-chunk 64, 2-stage cp.async.
// mode 0: out-proj (split-K via blockIdx.z, fp32 C0/C1 partials)
// mode 1: QKV — fused epilogue: RoPE (q,k) / transpose (v), direct to
//         g_q / g_k / g_v (region decided by n0).
// =====================================================================
#define STAGE_B 32768
#define GEMM_SMEM (2 * STAGE_B)
#define TP 130   // fp16 tile pitch in epilogue (odd word stride)

__global__ void __launch_bounds__(256, 2) gemm_f16(
    const __half* __restrict__ A, const __half* __restrict__ B,
    float* __restrict__ C0, float* __restrict__ C1,
    int ldC, int kLen, int mode)
{
    extern __shared__ char smem[];
    const uint32_t sb = smem_u32(smem);

    const int tid  = threadIdx.x;
    const int wid  = tid >> 5;
    const int lane = tid & 31;
    const int wm   = wid & 1;
    const int wn   = wid >> 1;
    const int m0 = blockIdx.y * 128;
    const int n0 = blockIdx.x * 128;
    const int kOff = blockIdx.z * kLen;

    float acc[4][4][4];
#pragma unroll
    for (int i = 0; i < 4; i++)
#pragma unroll
        for (int j = 0; j < 4; j++)
#pragma unroll
            for (int c = 0; c < 4; c++) acc[i][j][c] = 0.f;

    const int r  = tid >> 1;
    const int h2 = tid & 1;
    uint32_t dofs[4];
#pragma unroll
    for (int s = 0; s < 4; s++)
        dofs[s] = SWZ128((uint32_t)(r * 128 + h2 * 64 + s * 16));
    const __half* gA = A + (size_t)(m0 + r) * DMODEL + kOff + h2 * 32;
    const __half* gB = B + (size_t)(n0 + r) * DMODEL + kOff + h2 * 32;

    const int aRow = wm * 64 + (lane & 15);
    const int bRow = wn * 32 + (lane & 15);
    const int kb   = (lane >> 4) << 4;

    const int NCH = kLen / 64;

#define LOAD_STAGE(kc, st)                                                  \
    do {                                                                    \
        const uint32_t base = sb + (uint32_t)(st) * STAGE_B;                \
        _Pragma("unroll")                                                   \
        for (int s = 0; s < 4; s++) {                                       \
            cp16(base + dofs[s],         gA + (kc) + s * 8);                \
            cp16(base + 16384 + dofs[s], gB + (kc) + s * 8);                \
        }                                                                   \
    } while (0)

    LOAD_STAGE(0, 0);
    cp_commit();

    for (int it = 0; it < NCH; it++) {
        if (it + 1 < NCH) {
            LOAD_STAGE((it + 1) * 64, (it + 1) & 1);
            cp_commit();
            cp_wait<1>();
        } else {
            cp_wait<0>();
        }
        __syncthreads();

        const uint32_t bA = sb + (uint32_t)(it & 1) * STAGE_B;
        const uint32_t bB = bA + 16384;

#pragma unroll
        for (int kk = 0; kk < 4; kk++) {
            const uint32_t kby = (uint32_t)(kk * 32 + kb);
            uint32_t ah[4][4];
#pragma unroll
            for (int mt = 0; mt < 4; mt++) {
                const uint32_t row = (uint32_t)(aRow + mt * 16) * 128;
                ldsm_x4(ah[mt], bA + SWZ128(row + kby));
            }
#pragma unroll
            for (int ntp = 0; ntp < 2; ntp++) {
                const uint32_t row = (uint32_t)(bRow + ntp * 16) * 128;
                uint32_t bb[4];
                ldsm_x4(bb, bB + SWZ128(row + kby));
#pragma unroll
                for (int half = 0; half < 2; half++) {
                    const int nt = ntp * 2 + half;
                    uint32_t bf[2] = {bb[half], bb[half + 2]};
#pragma unroll
                    for (int mt = 0; mt < 4; mt++)
                        mma_f16(acc[mt][nt], ah[mt], bf);
                }
            }
        }
        __syncthreads();
    }

    const int g  = lane >> 2;
    const int tg = lane & 3;

    if (mode == 0) {
        float* __restrict__ C = blockIdx.z ? C1 : C0;
#pragma unroll
        for (int mt = 0; mt < 4; mt++) {
#pragma unroll
            for (int half = 0; half < 2; half++) {
                const int m = m0 + wm * 64 + mt * 16 + g + half * 8;
                float* cp = C + (size_t)m * ldC + n0 + wn * 32;
#pragma unroll
                for (int nt = 0; nt < 4; nt++) {
                    const int col = nt * 8 + tg * 2;
                    *(float2*)(cp + col) =
                        make_float2(acc[mt][nt][half * 2], acc[mt][nt][half * 2 + 1]);
                }
            }
        }
        return;
    }

    // ---------------- mode 1: fused QKV epilogue ----------------
    // stash tile as fp16 [128][TP] (odd word pitch -> conflict-free cols)
    __half* tsm = (__half*)smem;
#pragma unroll
    for (int mt = 0; mt < 4; mt++) {
#pragma unroll
        for (int half = 0; half < 2; half++) {
            const int rr = wm * 64 + mt * 16 + g + half * 8;
#pragma unroll
            for (int nt = 0; nt < 4; nt++) {
                const int cc = wn * 32 + nt * 8 + tg * 2;
                *(uint32_t*)(tsm + rr * TP + cc) =
                    pack_hf2(acc[mt][nt][half * 2], acc[mt][nt][half * 2 + 1]);
            }
        }
    }
    __syncthreads();

    const int region = n0 >> 10;     // 0=q, 1=k, 2=v
    if (region < 2) {
        __half* dst = region ? g_k : g_q;
        const float qs = region ? 1.f : 0.125f;
#pragma unroll
        for (int mt = 0; mt < 4; mt++) {
#pragma unroll
            for (int half = 0; half < 2; half++) {
                const int rr = wm * 64 + mt * 16 + g + half * 8;
                const int s = m0 + rr;
#pragma unroll
                for (int nt = 0; nt < 4; nt++) {
                    const int c  = wn * 32 + nt * 8 + tg * 2;
                    const int hd = c & 63;                  // head-dim (n0 1024-aligned blocks)
                    const int j  = hd & 31;
                    __half2 v2 = *(__half2*)(tsm + rr * TP + c);
                    __half2 p2 = *(__half2*)(tsm + rr * TP + (c ^ 32));
                    float2 cs0 = g_cs[(size_t)s * 32 + j];
                    float2 cs1 = g_cs[(size_t)s * 32 + j + 1];
                    float v0 = __half2float(v2.x), v1 = __half2float(v2.y);
                    float p0 = __half2float(p2.x), p1 = __half2float(p2.y);
                    float o0, o1;
                    if (hd < 32) {
                        o0 = v0 * cs0.x - p0 * cs0.y;
                        o1 = v1 * cs1.x - p1 * cs1.y;
                    } else {
                        o0 = v0 * cs0.x + p0 * cs0.y;
                        o1 = v1 * cs1.x + p1 * cs1.y;
                    }
                    const int rc = (n0 & 1023) + c;
                    *(uint32_t*)(dst + (size_t)s * DMODEL + rc) =
                        pack_hf2(o0 * qs, o1 * qs);
                }
            }
        }
    } else {
        // V transpose: thread -> output row c (v column), 64 s values
        const int c  = tid >> 1;
        const int sh = (tid & 1) * 64;
        const int gc = (n0 & 1023) + c;
        __half* dst = g_v + (size_t)gc * S_LEN + m0 + sh;
#pragma unroll
        for (int blk = 0; blk < 8; blk++) {
            uint4 u;
            uint32_t* up = (uint32_t*)&u;
#pragma unroll
            for (int p = 0; p < 4; p++) {
                __half2 t2;
                t2.x = tsm[(sh + blk * 8 + p * 2)     * TP + c];
                t2.y = tsm[(sh + blk * 8 + p * 2 + 1) * TP + c];
                up[p] = *(uint32_t*)&t2;
            }
            *(uint4*)(dst + blk * 8) = u;
        }
    }
}

// =====================================================================
// Windowed causal flash attention, FA2-style register softmax.
// q-tile 64, grid = (NHEADS, S_LEN/64), 128 threads = 4 warps.
// =====================================================================
#define AQ  0u
#define AK0 8192u
#define AK1 16384u
#define AV0 24576u
#define AV1 32768u
#define ATT_SMEM 40960

__global__ void __launch_bounds__(128, 4) attn_kernel()
{
    extern __shared__ char sm[];
    const uint32_t sb = smem_u32(sm);

    const int h   = blockIdx.x;
    const int q0  = blockIdx.y * 64;
    const int tid = threadIdx.x;
    const int wid = tid >> 5, lane = tid & 31;
    const int g = lane >> 2, tg = lane & 3;
    const int wrow = wid * 16;

    const int r2 = tid >> 1;
    const int s2 = (tid & 1) * 4;
    uint32_t tdofs[4];
#pragma unroll
    for (int s = 0; s < 4; s++)
        tdofs[s] = SWZ128((uint32_t)(r2 * 128 + (s2 + s) * 16));
#define ATL(dstbase, srcptr)                                   \
    do {                                                       \
        _Pragma("unroll")                                      \
        for (int s = 0; s < 4; s++)                            \
            cp16((dstbase) + tdofs[s], (srcptr) + s * 8);      \
    } while (0)

    const int kstart = (q0 - WINDOW) < 0 ? 0 : (q0 - WINDOW);
    const int nch = (q0 + 64 - kstart) / 64;

    ATL(sb + AQ,  g_q + (size_t)(q0 + r2) * DMODEL + h * 64 + s2 * 8);
    ATL(sb + AK0, g_k + (size_t)(kstart + r2) * DMODEL + h * 64 + s2 * 8);
    ATL(sb + AV0, g_v + (size_t)(h * 64 + r2) * S_LEN + kstart + s2 * 8);
    cp_commit();

    float o[8][4];
#pragma unroll
    for (int nt = 0; nt < 8; nt++)
#pragma unroll
        for (int c = 0; c < 4; c++) o[nt][c] = 0.f;
    float m0_ = -1e30f, m1_ = -1e30f, l0_ = 0.f, l1_ = 0.f;

    const int aRow = wrow + (lane & 15);
    const int bR15 = lane & 15;
    const int kb   = (lane >> 4) << 4;
    const int qrow0 = q0 + wrow + g;
    const int qrow1 = qrow0 + 8;
    const int qlo = q0 + wrow;
    const int qhi = qlo + 15;

    for (int it = 0; it < nch; it++) {
        const int kc = kstart + it * 64;
        const uint32_t KB = (it & 1) ? AK1 : AK0;
        const uint32_t VB = (it & 1) ? AV1 : AV0;
        const bool pf = (it + 1 < nch);

        cp_wait<0>();
        __syncthreads();
        if (pf) {
            const uint32_t KBn = (it & 1) ? AK0 : AK1;
            const uint32_t VBn = (it & 1) ? AV0 : AV1;
            ATL(sb + KBn, g_k + (size_t)(kc + 64 + r2) * DMODEL + h * 64 + s2 * 8);
            ATL(sb + VBn, g_v + (size_t)(h * 64 + r2) * S_LEN + kc + 64 + s2 * 8);
            cp_commit();
        }

        // ---- S = Q K^T ----
        float sacc[8][4];
#pragma unroll
        for (int nt = 0; nt < 8; nt++)
#pragma unroll
            for (int c = 0; c < 4; c++) sacc[nt][c] = 0.f;

#pragma unroll
        for (int kk = 0; kk < 4; kk++) {
            const uint32_t kby = (uint32_t)(kk * 32 + kb);
            uint32_t a[4];
            ldsm_x4(a, sb + AQ + SWZ128((uint32_t)aRow * 128 + kby));
#pragma unroll
            for (int ntp = 0; ntp < 4; ntp++) {
                uint32_t bb[4];
                ldsm_x4(bb, sb + KB + SWZ128((uint32_t)(ntp * 16 + bR15) * 128 + kby));
#pragma unroll
                for (int half = 0; half < 2; half++) {
                    uint32_t bf[2] = {bb[half], bb[half + 2]};
                    mma_f16(sacc[ntp * 2 + half], a, bf);
                }
            }
        }

        // ---- masking: warp-uniform skip for fully-interior chunks ----
        const bool needMask = !((kc + 63 <= qlo) && (kc >= qhi - WINDOW));
        if (needMask) {
#pragma unroll
            for (int nt = 0; nt < 8; nt++) {
                const int key0 = kc + nt * 8 + tg * 2;
                const int key1 = key0 + 1;
                const bool ok00 = (key0 <= qrow0) && (qrow0 - key0 <= WINDOW);
                const bool ok01 = (key1 <= qrow0) && (qrow0 - key1 <= WINDOW);
                const bool ok10 = (key0 <= qrow1) && (qrow1 - key0 <= WINDOW);
                const bool ok11 = (key1 <= qrow1) && (qrow1 - key1 <= WINDOW);
                sacc[nt][0] = ok00 ? sacc[nt][0] : -1e30f;
                sacc[nt][1] = ok01 ? sacc[nt][1] : -1e30f;
                sacc[nt][2] = ok10 ? sacc[nt][2] : -1e30f;
                sacc[nt][3] = ok11 ? sacc[nt][3] : -1e30f;
            }
        }

        // ---- warp-local online softmax ----
        float rmax0 = -1e30f, rmax1 = -1e30f;
#pragma unroll
        for (int nt = 0; nt < 8; nt++) {
            rmax0 = fmaxf(rmax0, fmaxf(sacc[nt][0], sacc[nt][1]));
            rmax1 = fmaxf(rmax1, fmaxf(sacc[nt][2], sacc[nt][3]));
        }
        rmax0 = fmaxf(rmax0, __shfl_xor_sync(0xffffffffu, rmax0, 1));
        rmax0 = fmaxf(rmax0, __shfl_xor_sync(0xffffffffu, rmax0, 2));
        rmax1 = fmaxf(rmax1, __shfl_xor_sync(0xffffffffu, rmax1, 1));
        rmax1 = fmaxf(rmax1, __shfl_xor_sync(0xffffffffu, rmax1, 2));

        const float mn0 = fmaxf(m0_, rmax0);
        const float mn1 = fmaxf(m1_, rmax1);
        const float sc0 = __expf(m0_ - mn0);
        const float sc1 = __expf(m1_ - mn1);
        float rs0 = 0.f, rs1 = 0.f;
#pragma unroll
        for (int nt = 0; nt < 8; nt++) {
            sacc[nt][0] = __expf(sacc[nt][0] - mn0);
            sacc[nt][1] = __expf(sacc[nt][1] - mn0);
            sacc[nt][2] = __expf(sacc[nt][2] - mn1);
            sacc[nt][3] = __expf(sacc[nt][3] - mn1);
            rs0 += sacc[nt][0] + sacc[nt][1];
            rs1 += sacc[nt][2] + sacc[nt][3];
        }
        rs0 += __shfl_xor_sync(0xffffffffu, rs0, 1);
        rs0 += __shfl_xor_sync(0xffffffffu, rs0, 2);
        rs1 += __shfl_xor_sync(0xffffffffu, rs1, 1);
        rs1 += __shfl_xor_sync(0xffffffffu, rs1, 2);
        l0_ = l0_ * sc0 + rs0; m0_ = mn0;
        l1_ = l1_ * sc1 + rs1; m1_ = mn1;

#pragma unroll
        for (int nt = 0; nt < 8; nt++) {
            o[nt][0] *= sc0; o[nt][1] *= sc0;
            o[nt][2] *= sc1; o[nt][3] *= sc1;
        }

        // ---- O += P V ----
#pragma unroll
        for (int kk = 0; kk < 4; kk++) {
            uint32_t pa[4];
            pa[0] = pack_hf2(sacc[2 * kk][0],     sacc[2 * kk][1]);
            pa[1] = pack_hf2(sacc[2 * kk][2],     sacc[2 * kk][3]);
            pa[2] = pack_hf2(sacc[2 * kk + 1][0], sacc[2 * kk + 1][1]);
            pa[3] = pack_hf2(sacc[2 * kk + 1][2], sacc[2 * kk + 1][3]);
            const uint32_t kby = (uint32_t)(kk * 32 + kb);
#pragma unroll
            for (int ntp = 0; ntp < 4; ntp++) {
                uint32_t bb[4];
                ldsm_x4(bb, sb + VB + SWZ128((uint32_t)(ntp * 16 + bR15) * 128 + kby));
#pragma unroll
                for (int half = 0; half < 2; half++) {
                    uint32_t bf[2] = {bb[half], bb[half + 2]};
                    mma_f16(o[ntp * 2 + half], pa, bf);
                }
            }
        }
    }

    const float iv0 = 1.f / l0_;
    const float iv1 = 1.f / l1_;
#pragma unroll
    for (int nt = 0; nt < 8; nt++) {
        const int col = h * 64 + nt * 8 + tg * 2;
        *(uint32_t*)(g_a16 + (size_t)qrow0 * DMODEL + col) =
            pack_hf2(o[nt][0] * iv0, o[nt][1] * iv0);
        *(uint32_t*)(g_a16 + (size_t)qrow1 * DMODEL + col) =
            pack_hf2(o[nt][2] * iv1, o[nt][3] * iv1);
    }
}

// =====================================================================
// LayerNorm with fused residual + split-K reduce
// =====================================================================
__global__ void __launch_bounds__(256) ln_kernel(
    const float* __restrict__ x,
    const float* __restrict__ gamma, const float* __restrict__ beta,
    float* __restrict__ y)
{
    const int s = blockIdx.x;
    const int tid = threadIdx.x;
    const size_t base = (size_t)s * DMODEL + tid * 4;

    float4 xv = *(const float4*)(x + base);
    float4 a  = *(const float4*)(g_o0 + base);
    float4 b4 = *(const float4*)(g_o1 + base);
    xv.x += a.x + b4.x;
    xv.y += a.y + b4.y;
    xv.z += a.z + b4.z;
    xv.w += a.w + b4.w;

    float s1 = xv.x + xv.y + xv.z + xv.w;
    float s2 = xv.x * xv.x + xv.y * xv.y + xv.z * xv.z + xv.w * xv.w;
#pragma unroll
    for (int o = 16; o >= 1; o >>= 1) {
        s1 += __shfl_xor_sync(0xffffffffu, s1, o);
        s2 += __shfl_xor_sync(0xffffffffu, s2, o);
    }
    __shared__ float a1[8], a2[8];
    const int w = tid >> 5, lane = tid & 31;
    if (lane == 0) { a1[w] = s1; a2[w] = s2; }
    __syncthreads();
    float t1 = 0.f, t2 = 0.f;
#pragma unroll
    for (int i = 0; i < 8; i++) { t1 += a1[i]; t2 += a2[i]; }

    const float mu  = t1 * (1.0f / DMODEL);
    const float var = t2 * (1.0f / DMODEL) - mu * mu;
    const float rstd = rsqrtf(var + LN_EPS);

    const int c = tid * 4;
    float4 gm = *(const float4*)(gamma + c);
    float4 bt = *(const float4*)(beta + c);
    float4 o;
    o.x = (xv.x - mu) * rstd * gm.x + bt.x;
    o.y = (xv.y - mu) * rstd * gm.y + bt.y;
    o.z = (xv.z - mu) * rstd * gm.z + bt.z;
    o.w = (xv.w - mu) * rstd * gm.w + bt.w;
    *(float4*)(y + (size_t)s * DMODEL + c) = o;
}

// =====================================================================
// launch — single stream, 5 kernels
// =====================================================================
extern "C" void kernel_launch(void* const* d_in, const int* in_sizes, int n_in,
                              void* d_out, int out_size)
{
    const float* x     = (const float*)d_in[0];
    const float* state = (const float*)d_in[1];
    const float* Wqkv  = (const float*)d_in[2];
    const float* Wout  = (const float*)d_in[3];
    const float* gamma = (const float*)d_in[4];
    const float* beta  = (const float*)d_in[5];
    float* y = (float*)d_out;

    float *o0, *o1;
    __half *x16, *a16, *wq, *wo;
    cudaGetSymbolAddress((void**)&o0,  g_o0);
    cudaGetSymbolAddress((void**)&o1,  g_o1);
    cudaGetSymbolAddress((void**)&x16, g_x16);
    cudaGetSymbolAddress((void**)&a16, g_a16);
    cudaGetSymbolAddress((void**)&wq,  g_wq);
    cudaGetSymbolAddress((void**)&wo,  g_wo);

    cudaFuncSetAttribute(gemm_f16, cudaFuncAttributeMaxDynamicSharedMemorySize, GEMM_SMEM);
    cudaFuncSetAttribute(attn_kernel, cudaFuncAttributeMaxDynamicSharedMemorySize, ATT_SMEM);

    // 0) fused prep: Wqkv^T + Wout^T + x->fp16 + cos/sin table
    prep_kernel<<<4864, 256>>>(x, Wqkv, Wout);

    // 1) QKV projection with fused RoPE / V-transpose epilogue
    gemm_f16<<<dim3(3 * DMODEL / 128, S_LEN / 128, 1), 256, GEMM_SMEM>>>(
        x16, wq, nullptr, nullptr, 0, DMODEL, 1);

    // 2) windowed attention (q-tile 64, 4 warps, mask-skip)
    attn_kernel<<<dim3(NHEADS, S_LEN / 64), 128, ATT_SMEM>>>();

    // 3) output projection, split-K=2 -> o0, o1
    gemm_f16<<<dim3(DMODEL / 128, S_LEN / 128, 2), 256, GEMM_SMEM>>>(
        a16, wo, o0, o1, DMODEL, DMODEL / 2, 0);

    // 4) LayerNorm (fused residual + split-K reduce) -> y
    ln_kernel<<<S_LEN, 256>>>(x, gamma, beta, y);

    // 5) pass-through state if the output buffer includes it
    if (out_size >= S_LEN * DMODEL + DMODEL) {
        cudaMemcpyAsync(y + (size_t)S_LEN * DMODEL, state,
                        DMODEL * sizeof(float), cudaMemcpyDeviceToDevice);
    }
}